// round 10
// baseline (speedup 1.0000x reference)
#include <cuda_runtime.h>
#include <cuda_fp16.h>
#include <math.h>
#include <stdint.h>

#define B_    2
#define N_    1024
#define D_    1024
#define H_    16
#define DH_   64
#define MLP_  4096
#define DEPTH_ 6
#define M_    (B_ * N_)   /* 2048 rows */

// ---------------- scratch -----------------------------------------------
__device__ __half g_h  [(size_t)M_ * D_];
__device__ __half g_qkv[(size_t)M_ * 3 * D_];
__device__ __half g_attn[(size_t)B_ * H_ * N_ * N_];
__device__ __half g_vt [(size_t)B_ * H_ * DH_ * N_];
__device__ __half g_o  [(size_t)M_ * D_];
__device__ __half g_mlp[(size_t)M_ * MLP_];
__device__ __half g_wqkv[(size_t)DEPTH_ * D_ * 3 * D_];
__device__ __half g_wout[(size_t)DEPTH_ * D_ * D_];
__device__ __half g_w1  [(size_t)DEPTH_ * D_ * MLP_];
__device__ __half g_w2  [(size_t)DEPTH_ * MLP_ * D_];

// ---------------- helpers ---------------------------------------------------
__device__ __forceinline__ void mma16(float* d, const uint32_t* a, const uint32_t* b) {
    asm volatile(
        "mma.sync.aligned.m16n8k16.row.col.f32.f16.f16.f32 "
        "{%0,%1,%2,%3},{%4,%5,%6,%7},{%8,%9},{%0,%1,%2,%3};"
        : "+f"(d[0]), "+f"(d[1]), "+f"(d[2]), "+f"(d[3])
        : "r"(a[0]), "r"(a[1]), "r"(a[2]), "r"(a[3]),
          "r"(b[0]), "r"(b[1]));
}
__device__ __forceinline__ void ldm4(uint32_t* r, uint32_t addr) {
    asm volatile("ldmatrix.sync.aligned.m8n8.x4.shared.b16 {%0,%1,%2,%3}, [%4];"
        : "=r"(r[0]), "=r"(r[1]), "=r"(r[2]), "=r"(r[3]) : "r"(addr));
}
__device__ __forceinline__ void cp16(void* smem_dst, const void* gmem_src) {
    uint32_t dst = (uint32_t)__cvta_generic_to_shared(smem_dst);
    asm volatile("cp.async.cg.shared.global [%0], [%1], 16;"
                 :: "r"(dst), "l"(gmem_src));
}
__device__ __forceinline__ void cp_commit() {
    asm volatile("cp.async.commit_group;");
}

// ---------------- weight pre-pass: [K,N] fp32 -> [N,K] fp16 -----------------
__global__ void __launch_bounds__(256) wtrans_kernel(
    const float* __restrict__ src, __half* __restrict__ dst, int K, int N)
{
    __shared__ float t[32][33];
    int n0 = blockIdx.x * 32, k0 = blockIdx.y * 32;
    src += (size_t)blockIdx.z * K * N;
    dst += (size_t)blockIdx.z * K * N;
    int tx = threadIdx.x & 31, ty = threadIdx.x >> 5;
#pragma unroll
    for (int i = ty; i < 32; i += 8)
        t[i][tx] = src[(size_t)(k0 + i) * N + n0 + tx];
    __syncthreads();
#pragma unroll
    for (int i = ty; i < 32; i += 8)
        dst[(size_t)(n0 + i) * K + k0 + tx] = __float2half_rn(t[tx][i]);
}

// ---------------- V transpose: qkv fp16 -> Vt[bh][d][j] ---------------------
__global__ void __launch_bounds__(256) vtrans_kernel(
    const __half* __restrict__ qkv, __half* __restrict__ vt)
{
    __shared__ __half t[64][66];
    int bh = blockIdx.y;
    int b = bh >> 4, h = bh & 15;
    int j0 = blockIdx.x * 64;
    const __half* src = qkv + (size_t)b * N_ * 3 * D_ + 2 * D_ + (size_t)h * DH_;
    __half* dst = vt + (size_t)bh * DH_ * N_;
    int tid = threadIdx.x;
#pragma unroll
    for (int i = 0; i < 16; i++) {
        int idx = tid + i * 256;
        int j = idx >> 6, d = idx & 63;
        t[j][d] = src[(size_t)(j0 + j) * 3 * D_ + d];
    }
    __syncthreads();
#pragma unroll
    for (int i = 0; i < 16; i++) {
        int idx = tid + i * 256;
        int d = idx >> 6, j = idx & 63;
        dst[(size_t)d * N_ + j0 + j] = t[j][d];
    }
}

// ---------------- LayerNorm (emits fp16) -----------------------------------
__global__ void __launch_bounds__(256) ln_kernel(
    const float* __restrict__ x, const float* __restrict__ s,
    const float* __restrict__ b, __half* __restrict__ o)
{
    __shared__ float red[2][8];
    int row = blockIdx.x;
    const float* xr = x + (size_t)row * D_;
    __half* orow = o + (size_t)row * D_;
    int t = threadIdx.x;
    float v[4];
    float sum = 0.f, sq = 0.f;
#pragma unroll
    for (int i = 0; i < 4; i++) {
        float z = xr[t + i * 256];
        v[i] = z; sum += z; sq += z * z;
    }
#pragma unroll
    for (int off = 16; off > 0; off >>= 1) {
        sum += __shfl_xor_sync(0xffffffffu, sum, off);
        sq  += __shfl_xor_sync(0xffffffffu, sq,  off);
    }
    if ((t & 31) == 0) { red[0][t >> 5] = sum; red[1][t >> 5] = sq; }
    __syncthreads();
    sum = 0.f; sq = 0.f;
#pragma unroll
    for (int i = 0; i < 8; i++) { sum += red[0][i]; sq += red[1][i]; }
    float mean = sum * (1.f / D_);
    float var  = sq  * (1.f / D_) - mean * mean;
    float rstd = rsqrtf(var + 1e-5f);
#pragma unroll
    for (int i = 0; i < 4; i++) {
        int c = t + i * 256;
        orow[c] = __float2half_rn((v[i] - mean) * rstd * s[c] + b[c]);
    }
}

// ---------------- fp16 tensor-core GEMM (ldmatrix + cp.async) ---------------
template<int BN, int WM, int WN, int EPI, int OH>
__global__ void __launch_bounds__(256, 1) gemm_hf(
    const __half* __restrict__ A, const __half* __restrict__ Wt,
    const float* __restrict__ bias, const float* __restrict__ res,
    void* __restrict__ Cv, int M, int N, int K)
{
    const int MI = WM / 16, NI = WN / 8;
    const int WN_CNT = BN / WN;
    const int RS = 144;
    const int A_BYTES = 128 * RS;
    const int B_BYTES = BN * RS;

    extern __shared__ char sm[];
    char* Asm = sm;
    char* Bsm = sm + 2 * A_BYTES;

    int tid = threadIdx.x;
    int bx = blockIdx.x, by = blockIdx.y;
    int wid = tid >> 5, lane = tid & 31;
    int wn = wid % WN_CNT, wm = wid / WN_CNT;
    int g = lane >> 2, q = lane & 3;
    int quad = lane >> 3, lr = lane & 7;

    uint32_t as_base = (uint32_t)__cvta_generic_to_shared(Asm);
    uint32_t bs_base = (uint32_t)__cvta_generic_to_shared(Bsm);
    // ldmatrix per-lane offsets (A: 16x16 fragment; B: two 8x16 n-tiles)
    uint32_t aoff = (uint32_t)((wm * WM + (quad & 1) * 8 + lr) * RS + (quad >> 1) * 16);
    uint32_t boff = (uint32_t)((wn * WN + (quad >> 1) * 8 + lr) * RS + (quad & 1) * 16);

    const __half* Ab = A  + (size_t)by * 128 * K;
    const __half* Bb = Wt + (size_t)bx * BN  * K;
    int KT = K / 64;

    float acc[MI][NI][4];
#pragma unroll
    for (int mi = 0; mi < MI; mi++)
#pragma unroll
        for (int ni = 0; ni < NI; ni++)
#pragma unroll
            for (int k = 0; k < 4; k++) acc[mi][ni][k] = 0.f;

    auto load_tile = [&](int kt, int s) {
#pragma unroll
        for (int i = 0; i < 4; i++) {
            int idx = tid + i * 256;
            int r = idx >> 3, c = idx & 7;
            cp16(Asm + s * A_BYTES + r * RS + c * 16,
                 Ab + (size_t)r * K + kt * 64 + c * 8);
        }
#pragma unroll
        for (int i = 0; i < BN / 32; i++) {
            int idx = tid + i * 256;
            int r = idx >> 3, c = idx & 7;
            cp16(Bsm + s * B_BYTES + r * RS + c * 16,
                 Bb + (size_t)r * K + kt * 64 + c * 8);
        }
        cp_commit();
    };

    load_tile(0, 0);

    for (int kt = 0; kt < KT; kt++) {
        int s = kt & 1;
        if (kt + 1 < KT) {
            load_tile(kt + 1, (kt + 1) & 1);
            asm volatile("cp.async.wait_group 1;");
        } else {
            asm volatile("cp.async.wait_group 0;");
        }
        __syncthreads();
        uint32_t As32 = as_base + s * A_BYTES + aoff;
        uint32_t Bs32 = bs_base + s * B_BYTES + boff;
#pragma unroll
        for (int ks = 0; ks < 4; ks++) {
            int kb = ks * 32;
            uint32_t a[MI][4];
#pragma unroll
            for (int mi = 0; mi < MI; mi++)
                ldm4(a[mi], As32 + mi * 16 * RS + kb);
            uint32_t b[NI][2];
#pragma unroll
            for (int pi = 0; pi < NI / 2; pi++) {
                uint32_t t4[4];
                ldm4(t4, Bs32 + pi * 16 * RS + kb);
                b[2 * pi][0] = t4[0]; b[2 * pi][1] = t4[1];
                b[2 * pi + 1][0] = t4[2]; b[2 * pi + 1][1] = t4[3];
            }
#pragma unroll
            for (int mi = 0; mi < MI; mi++)
#pragma unroll
                for (int ni = 0; ni < NI; ni++) mma16(acc[mi][ni], a[mi], b[ni]);
        }
        __syncthreads();
    }

#pragma unroll
    for (int mi = 0; mi < MI; mi++) {
        int r0 = by * 128 + wm * WM + mi * 16 + g;
#pragma unroll
        for (int ni = 0; ni < NI; ni++) {
            int c = bx * BN + wn * WN + ni * 8 + q * 2;
            float2 v0 = make_float2(acc[mi][ni][0], acc[mi][ni][1]);
            float2 v1 = make_float2(acc[mi][ni][2], acc[mi][ni][3]);
            if (EPI & 1) {
                float b0 = bias[c], b1 = bias[c + 1];
                v0.x += b0; v0.y += b1; v1.x += b0; v1.y += b1;
            }
            if (EPI & 2) {
                const float is2 = 0.70710678118654752f;
                v0.x = 0.5f * v0.x * (1.f + erff(v0.x * is2));
                v0.y = 0.5f * v0.y * (1.f + erff(v0.y * is2));
                v1.x = 0.5f * v1.x * (1.f + erff(v1.x * is2));
                v1.y = 0.5f * v1.y * (1.f + erff(v1.y * is2));
            }
            size_t a0 = (size_t)r0 * N + c;
            size_t a1 = (size_t)(r0 + 8) * N + c;
            if (EPI & 4) {
                float2 r0v = *(const float2*)(res + a0);
                float2 r1v = *(const float2*)(res + a1);
                v0.x += r0v.x; v0.y += r0v.y; v1.x += r1v.x; v1.y += r1v.y;
            }
            if (OH) {
                __half* C = (__half*)Cv;
                *(__half2*)(C + a0) = __floats2half2_rn(v0.x, v0.y);
                *(__half2*)(C + a1) = __floats2half2_rn(v1.x, v1.y);
            } else {
                float* C = (float*)Cv;
                *(float2*)(C + a0) = v0;
                *(float2*)(C + a1) = v1;
            }
        }
    }
}

// ---------------- attention scores (fp16 mma + ldmatrix) --------------------
__global__ void __launch_bounds__(256, 1) scores_hf(
    const __half* __restrict__ qkv, __half* __restrict__ attn)
{
    const int RS = 144;
    extern __shared__ char sm[];
    char* Qs = sm;
    char* Ks = sm + 128 * RS;

    int bh = blockIdx.z;
    int b = bh >> 4, h = bh & 15;
    int i0 = blockIdx.y * 128, j0 = blockIdx.x * 128;
    const __half* Qb = qkv + (size_t)b * N_ * 3 * D_ + (size_t)h * DH_;
    const __half* Kb = Qb + D_;

    int tid = threadIdx.x;
    int wid = tid >> 5, lane = tid & 31;
    int wm = wid >> 1, wn = wid & 1;      // WM=32, WN=64
    int g = lane >> 2, q = lane & 3;
    int quad = lane >> 3, lr = lane & 7;

    uint32_t qs_base = (uint32_t)__cvta_generic_to_shared(Qs);
    uint32_t ks_base = (uint32_t)__cvta_generic_to_shared(Ks);
    uint32_t aoff = (uint32_t)((wm * 32 + (quad & 1) * 8 + lr) * RS + (quad >> 1) * 16);
    uint32_t boff = (uint32_t)((wn * 64 + (quad >> 1) * 8 + lr) * RS + (quad & 1) * 16);

#pragma unroll
    for (int i = 0; i < 4; i++) {
        int idx = tid + i * 256;
        int r = idx >> 3, c = idx & 7;
        cp16(Qs + r * RS + c * 16, Qb + (size_t)(i0 + r) * 3 * D_ + c * 8);
        cp16(Ks + r * RS + c * 16, Kb + (size_t)(j0 + r) * 3 * D_ + c * 8);
    }
    cp_commit();
    asm volatile("cp.async.wait_group 0;");
    __syncthreads();

    float acc[2][8][4];
#pragma unroll
    for (int mi = 0; mi < 2; mi++)
#pragma unroll
        for (int ni = 0; ni < 8; ni++)
#pragma unroll
            for (int k = 0; k < 4; k++) acc[mi][ni][k] = 0.f;

#pragma unroll
    for (int ks = 0; ks < 4; ks++) {
        int kb = ks * 32;
        uint32_t a[2][4];
#pragma unroll
        for (int mi = 0; mi < 2; mi++)
            ldm4(a[mi], qs_base + aoff + mi * 16 * RS + kb);
        uint32_t br[8][2];
#pragma unroll
        for (int pi = 0; pi < 4; pi++) {
            uint32_t t4[4];
            ldm4(t4, ks_base + boff + pi * 16 * RS + kb);
            br[2 * pi][0] = t4[0]; br[2 * pi][1] = t4[1];
            br[2 * pi + 1][0] = t4[2]; br[2 * pi + 1][1] = t4[3];
        }
#pragma unroll
        for (int mi = 0; mi < 2; mi++)
#pragma unroll
            for (int ni = 0; ni < 8; ni++) mma16(acc[mi][ni], a[mi], br[ni]);
    }

    const float scale = 0.03125f;   // D^-0.5 (full-dim per reference)
    __half* Ao = attn + (size_t)bh * N_ * N_;
#pragma unroll
    for (int mi = 0; mi < 2; mi++) {
        int r0 = i0 + wm * 32 + mi * 16 + g;
#pragma unroll
        for (int ni = 0; ni < 8; ni++) {
            int c = j0 + wn * 64 + ni * 8 + q * 2;
            *(__half2*)(Ao + (size_t)r0 * N_ + c) =
                __floats2half2_rn(acc[mi][ni][0] * scale, acc[mi][ni][1] * scale);
            *(__half2*)(Ao + (size_t)(r0 + 8) * N_ + c) =
                __floats2half2_rn(acc[mi][ni][2] * scale, acc[mi][ni][3] * scale);
        }
    }
}

// ---------------- row softmax over N=1024 (fp16 storage) --------------------
__global__ void __launch_bounds__(256) softmax_hf(__half* __restrict__ attn)
{
    __shared__ float red[8];
    size_t row = blockIdx.x;
    __half* p = attn + row * N_;
    int t = threadIdx.x;
    float v[4];
    float mx = -1e30f;
#pragma unroll
    for (int i = 0; i < 4; i++) {
        v[i] = __half2float(p[t + i * 256]);
        mx = fmaxf(mx, v[i]);
    }
#pragma unroll
    for (int off = 16; off > 0; off >>= 1)
        mx = fmaxf(mx, __shfl_xor_sync(0xffffffffu, mx, off));
    if ((t & 31) == 0) red[t >> 5] = mx;
    __syncthreads();
    mx = red[0];
#pragma unroll
    for (int i = 1; i < 8; i++) mx = fmaxf(mx, red[i]);
    __syncthreads();
    float sum = 0.f;
#pragma unroll
    for (int i = 0; i < 4; i++) { v[i] = __expf(v[i] - mx); sum += v[i]; }
#pragma unroll
    for (int off = 16; off > 0; off >>= 1)
        sum += __shfl_xor_sync(0xffffffffu, sum, off);
    if ((t & 31) == 0) red[t >> 5] = sum;
    __syncthreads();
    sum = 0.f;
#pragma unroll
    for (int i = 0; i < 8; i++) sum += red[i];
    float inv = 1.f / sum;
#pragma unroll
    for (int i = 0; i < 4; i++) p[t + i * 256] = __float2half_rn(v[i] * inv);
}

// ---------------- O = attn @ Vt^T (fp16 mma + ldmatrix) ---------------------
__global__ void __launch_bounds__(256, 1) av_hf(
    const __half* __restrict__ attn, const __half* __restrict__ vt,
    __half* __restrict__ o)
{
    const int RS = 144;
    const int A_BYTES = 128 * RS;
    const int B_BYTES = 64 * RS;
    extern __shared__ char sm[];
    char* Asm = sm;
    char* Bsm = sm + 2 * A_BYTES;

    int bh = blockIdx.y;
    int b = bh >> 4, h = bh & 15;
    int i0 = blockIdx.x * 128;
    const __half* Ab = attn + (size_t)bh * N_ * N_ + (size_t)i0 * N_;
    const __half* Bb = vt + (size_t)bh * DH_ * N_;

    int tid = threadIdx.x;
    int wid = tid >> 5, lane = tid & 31;
    int wm = wid >> 1, wn = wid & 1;      // WM=32, WN=32
    int g = lane >> 2, q = lane & 3;
    int quad = lane >> 3, lr = lane & 7;

    uint32_t as_base = (uint32_t)__cvta_generic_to_shared(Asm);
    uint32_t bs_base = (uint32_t)__cvta_generic_to_shared(Bsm);
    uint32_t aoff = (uint32_t)((wm * 32 + (quad & 1) * 8 + lr) * RS + (quad >> 1) * 16);
    uint32_t boff = (uint32_t)((wn * 32 + (quad >> 1) * 8 + lr) * RS + (quad & 1) * 16);

    float acc[2][4][4];
#pragma unroll
    for (int mi = 0; mi < 2; mi++)
#pragma unroll
        for (int ni = 0; ni < 4; ni++)
#pragma unroll
            for (int k = 0; k < 4; k++) acc[mi][ni][k] = 0.f;

    auto load_tile = [&](int kt, int s) {
#pragma unroll
        for (int i = 0; i < 4; i++) {
            int idx = tid + i * 256;
            int r = idx >> 3, c = idx & 7;
            cp16(Asm + s * A_BYTES + r * RS + c * 16,
                 Ab + (size_t)r * N_ + kt * 64 + c * 8);
        }
#pragma unroll
        for (int i = 0; i < 2; i++) {
            int idx = tid + i * 256;
            int r = idx >> 3, c = idx & 7;
            cp16(Bsm + s * B_BYTES + r * RS + c * 16,
                 Bb + (size_t)r * N_ + kt * 64 + c * 8);
        }
        cp_commit();
    };

    load_tile(0, 0);

    for (int kt = 0; kt < 16; kt++) {
        int s = kt & 1;
        if (kt + 1 < 16) {
            load_tile(kt + 1, (kt + 1) & 1);
            asm volatile("cp.async.wait_group 1;");
        } else {
            asm volatile("cp.async.wait_group 0;");
        }
        __syncthreads();
        uint32_t As32 = as_base + s * A_BYTES + aoff;
        uint32_t Bs32 = bs_base + s * B_BYTES + boff;
#pragma unroll
        for (int ks = 0; ks < 4; ks++) {
            int kb = ks * 32;
            uint32_t a[2][4];
#pragma unroll
            for (int mi = 0; mi < 2; mi++)
                ldm4(a[mi], As32 + mi * 16 * RS + kb);
            uint32_t br[4][2];
#pragma unroll
            for (int pi = 0; pi < 2; pi++) {
                uint32_t t4[4];
                ldm4(t4, Bs32 + pi * 16 * RS + kb);
                br[2 * pi][0] = t4[0]; br[2 * pi][1] = t4[1];
                br[2 * pi + 1][0] = t4[2]; br[2 * pi + 1][1] = t4[3];
            }
#pragma unroll
            for (int mi = 0; mi < 2; mi++)
#pragma unroll
                for (int ni = 0; ni < 4; ni++) mma16(acc[mi][ni], a[mi], br[ni]);
        }
        __syncthreads();
    }

#pragma unroll
    for (int mi = 0; mi < 2; mi++) {
        int r0 = i0 + wm * 32 + mi * 16 + g;
#pragma unroll
        for (int ni = 0; ni < 4; ni++) {
            int c = h * DH_ + wn * 32 + ni * 8 + q * 2;
            size_t a0 = ((size_t)b * N_ + r0) * D_ + c;
            size_t a1 = ((size_t)b * N_ + r0 + 8) * D_ + c;
            *(__half2*)(o + a0) = __floats2half2_rn(acc[mi][ni][0], acc[mi][ni][1]);
            *(__half2*)(o + a1) = __floats2half2_rn(acc[mi][ni][2], acc[mi][ni][3]);
        }
    }
}

// ---------------- orchestration --------------------------------------------
#define HF_SMEM_256 (2 * (128 * 144) + 2 * (256 * 144))   /* 110592 */
#define HF_SMEM_128 (2 * (128 * 144) + 2 * (128 * 144))   /*  73728 */
#define SC_SMEM     (2 * (128 * 144))                     /*  36864 */
#define AV_SMEM     (2 * (128 * 144) + 2 * (64 * 144))    /*  55296 */

extern "C" void kernel_launch(void* const* d_in, const int* in_sizes, int n_in,
                              void* d_out, int out_size)
{
    (void)in_sizes; (void)n_in; (void)out_size;
    const float* x     = (const float*)d_in[0];
    const float* ln1_s = (const float*)d_in[1];
    const float* ln1_b = (const float*)d_in[2];
    const float* w_qkv = (const float*)d_in[3];
    const float* w_out = (const float*)d_in[4];
    const float* b_out = (const float*)d_in[5];
    const float* ln2_s = (const float*)d_in[6];
    const float* ln2_b = (const float*)d_in[7];
    const float* w1    = (const float*)d_in[8];
    const float* b1    = (const float*)d_in[9];
    const float* w2    = (const float*)d_in[10];
    const float* b2    = (const float*)d_in[11];
    float* out = (float*)d_out;

    __half *h, *qkv, *attn, *vt, *o, *mlp, *wqkv, *wout, *w1t, *w2t;
    cudaGetSymbolAddress((void**)&h,    g_h);
    cudaGetSymbolAddress((void**)&qkv,  g_qkv);
    cudaGetSymbolAddress((void**)&attn, g_attn);
    cudaGetSymbolAddress((void**)&vt,   g_vt);
    cudaGetSymbolAddress((void**)&o,    g_o);
    cudaGetSymbolAddress((void**)&mlp,  g_mlp);
    cudaGetSymbolAddress((void**)&wqkv, g_wqkv);
    cudaGetSymbolAddress((void**)&wout, g_wout);
    cudaGetSymbolAddress((void**)&w1t,  g_w1);
    cudaGetSymbolAddress((void**)&w2t,  g_w2);

    cudaFuncSetAttribute(gemm_hf<256, 64, 64, 0, 1>,
        cudaFuncAttributeMaxDynamicSharedMemorySize, HF_SMEM_256);
    cudaFuncSetAttribute(gemm_hf<256, 64, 64, 3, 1>,
        cudaFuncAttributeMaxDynamicSharedMemorySize, HF_SMEM_256);
    cudaFuncSetAttribute(gemm_hf<128, 32, 64, 5, 0>,
        cudaFuncAttributeMaxDynamicSharedMemorySize, HF_SMEM_128);
    cudaFuncSetAttribute(scores_hf,
        cudaFuncAttributeMaxDynamicSharedMemorySize, SC_SMEM);
    cudaFuncSetAttribute(av_hf,
        cudaFuncAttributeMaxDynamicSharedMemorySize, AV_SMEM);

    // pre-pass: weights -> [N][K] fp16
    wtrans_kernel<<<dim3(3 * D_ / 32, D_ / 32, DEPTH_), 256>>>(w_qkv, wqkv, D_, 3 * D_);
    wtrans_kernel<<<dim3(D_ / 32, D_ / 32, DEPTH_), 256>>>(w_out, wout, D_, D_);
    wtrans_kernel<<<dim3(MLP_ / 32, D_ / 32, DEPTH_), 256>>>(w1, w1t, D_, MLP_);
    wtrans_kernel<<<dim3(D_ / 32, MLP_ / 32, DEPTH_), 256>>>(w2, w2t, MLP_, D_);

    cudaMemcpyAsync(out, x, (size_t)M_ * D_ * sizeof(float),
                    cudaMemcpyDeviceToDevice);

    for (int l = 0; l < DEPTH_; l++) {
        // --- attention block ---
        ln_kernel<<<M_, 256>>>(out, ln1_s + (size_t)l * D_, ln1_b + (size_t)l * D_, h);
        gemm_hf<256, 64, 64, 0, 1><<<dim3(3 * D_ / 256, M_ / 128), 256, HF_SMEM_256>>>(
            h, wqkv + (size_t)l * D_ * 3 * D_, nullptr, nullptr,
            qkv, M_, 3 * D_, D_);
        vtrans_kernel<<<dim3(N_ / 64, B_ * H_), 256>>>(qkv, vt);
        scores_hf<<<dim3(8, 8, B_ * H_), 256, SC_SMEM>>>(qkv, attn);
        softmax_hf<<<B_ * H_ * N_, 256>>>(attn);
        av_hf<<<dim3(N_ / 128, B_ * H_), 256, AV_SMEM>>>(attn, vt, o);
        gemm_hf<128, 32, 64, 5, 0><<<dim3(D_ / 128, M_ / 128), 256, HF_SMEM_128>>>(
            o, wout + (size_t)l * D_ * D_, b_out + (size_t)l * D_,
            out, out, M_, D_, D_);
        // --- MLP block ---
        ln_kernel<<<M_, 256>>>(out, ln2_s + (size_t)l * D_, ln2_b + (size_t)l * D_, h);
        gemm_hf<256, 64, 64, 3, 1><<<dim3(MLP_ / 256, M_ / 128), 256, HF_SMEM_256>>>(
            h, w1t + (size_t)l * D_ * MLP_, b1 + (size_t)l * MLP_,
            nullptr, mlp, M_, MLP_, D_);
        gemm_hf<128, 32, 64, 5, 0><<<dim3(D_ / 128, M_ / 128), 256, HF_SMEM_128>>>(
            mlp, w2t + (size_t)l * MLP_ * D_, b2 + (size_t)l * D_,
            out, out, M_, D_, MLP_);
    }
}

// round 11
// speedup vs baseline: 1.0755x; 1.0755x over previous
#include <cuda_runtime.h>
#include <cuda_fp16.h>
#include <math.h>
#include <stdint.h>

#define B_    2
#define N_    1024
#define D_    1024
#define H_    16
#define DH_   64
#define MLP_  4096
#define DEPTH_ 6
#define M_    (B_ * N_)   /* 2048 rows */

// ---------------- scratch -----------------------------------------------
__device__ __half g_h  [(size_t)M_ * D_];
__device__ __half g_qkv[(size_t)M_ * 3 * D_];
__device__ __half g_attn[(size_t)B_ * H_ * N_ * N_];
__device__ __half g_vt [(size_t)B_ * H_ * DH_ * N_];
__device__ __half g_o  [(size_t)M_ * D_];
__device__ __half g_mlp[(size_t)M_ * MLP_];
__device__ __half g_wqkv[(size_t)DEPTH_ * D_ * 3 * D_];
__device__ __half g_wout[(size_t)DEPTH_ * D_ * D_];
__device__ __half g_w1  [(size_t)DEPTH_ * D_ * MLP_];
__device__ __half g_w2  [(size_t)DEPTH_ * MLP_ * D_];

// ---------------- helpers ---------------------------------------------------
__device__ __forceinline__ void mma16(float* d, const uint32_t* a, const uint32_t* b) {
    asm volatile(
        "mma.sync.aligned.m16n8k16.row.col.f32.f16.f16.f32 "
        "{%0,%1,%2,%3},{%4,%5,%6,%7},{%8,%9},{%0,%1,%2,%3};"
        : "+f"(d[0]), "+f"(d[1]), "+f"(d[2]), "+f"(d[3])
        : "r"(a[0]), "r"(a[1]), "r"(a[2]), "r"(a[3]),
          "r"(b[0]), "r"(b[1]));
}
__device__ __forceinline__ void cp16(void* smem_dst, const void* gmem_src) {
    uint32_t dst = (uint32_t)__cvta_generic_to_shared(smem_dst);
    asm volatile("cp.async.cg.shared.global [%0], [%1], 16;"
                 :: "r"(dst), "l"(gmem_src));
}
__device__ __forceinline__ void cp_commit() {
    asm volatile("cp.async.commit_group;");
}

// ---------------- weight pre-pass: [K,N] fp32 -> [N,K] fp16 -----------------
__global__ void __launch_bounds__(256) wtrans_kernel(
    const float* __restrict__ src, __half* __restrict__ dst, int K, int N)
{
    __shared__ float t[32][33];
    int n0 = blockIdx.x * 32, k0 = blockIdx.y * 32;
    src += (size_t)blockIdx.z * K * N;
    dst += (size_t)blockIdx.z * K * N;
    int tx = threadIdx.x & 31, ty = threadIdx.x >> 5;
#pragma unroll
    for (int i = ty; i < 32; i += 8)
        t[i][tx] = src[(size_t)(k0 + i) * N + n0 + tx];
    __syncthreads();
#pragma unroll
    for (int i = ty; i < 32; i += 8)
        dst[(size_t)(n0 + i) * K + k0 + tx] = __float2half_rn(t[tx][i]);
}

// ---------------- V transpose: qkv fp16 -> Vt[bh][d][j] ---------------------
__global__ void __launch_bounds__(256) vtrans_kernel(
    const __half* __restrict__ qkv, __half* __restrict__ vt)
{
    __shared__ __half t[64][66];
    int bh = blockIdx.y;
    int b = bh >> 4, h = bh & 15;
    int j0 = blockIdx.x * 64;
    const __half* src = qkv + (size_t)b * N_ * 3 * D_ + 2 * D_ + (size_t)h * DH_;
    __half* dst = vt + (size_t)bh * DH_ * N_;
    int tid = threadIdx.x;
#pragma unroll
    for (int i = 0; i < 16; i++) {
        int idx = tid + i * 256;
        int j = idx >> 6, d = idx & 63;
        t[j][d] = src[(size_t)(j0 + j) * 3 * D_ + d];
    }
    __syncthreads();
#pragma unroll
    for (int i = 0; i < 16; i++) {
        int idx = tid + i * 256;
        int d = idx >> 6, j = idx & 63;
        dst[(size_t)d * N_ + j0 + j] = t[j][d];
    }
}

// ---------------- LayerNorm (emits fp16) -----------------------------------
__global__ void __launch_bounds__(256) ln_kernel(
    const float* __restrict__ x, const float* __restrict__ s,
    const float* __restrict__ b, __half* __restrict__ o)
{
    __shared__ float red[2][8];
    int row = blockIdx.x;
    const float* xr = x + (size_t)row * D_;
    __half* orow = o + (size_t)row * D_;
    int t = threadIdx.x;
    float v[4];
    float sum = 0.f, sq = 0.f;
#pragma unroll
    for (int i = 0; i < 4; i++) {
        float z = xr[t + i * 256];
        v[i] = z; sum += z; sq += z * z;
    }
#pragma unroll
    for (int off = 16; off > 0; off >>= 1) {
        sum += __shfl_xor_sync(0xffffffffu, sum, off);
        sq  += __shfl_xor_sync(0xffffffffu, sq,  off);
    }
    if ((t & 31) == 0) { red[0][t >> 5] = sum; red[1][t >> 5] = sq; }
    __syncthreads();
    sum = 0.f; sq = 0.f;
#pragma unroll
    for (int i = 0; i < 8; i++) { sum += red[0][i]; sq += red[1][i]; }
    float mean = sum * (1.f / D_);
    float var  = sq  * (1.f / D_) - mean * mean;
    float rstd = rsqrtf(var + 1e-5f);
#pragma unroll
    for (int i = 0; i < 4; i++) {
        int c = t + i * 256;
        orow[c] = __float2half_rn((v[i] - mean) * rstd * s[c] + b[c]);
    }
}

// ---------------- fp16 tensor-core GEMM, cp.async, 2 CTAs/SM ----------------
// A: [M][K] fp16. Wt: [N][K] fp16. BM=128, BN=128, BK=64, 256 thr (8 warps,
// 4m x 2n, warp tile 32x64). Smem rows 144B -> conflict-free fragment loads.
// EPI bit0:+bias bit1:gelu bit2:+res.  OH: write __half output.
template<int EPI, int OH>
__global__ void __launch_bounds__(256, 2) gemm_hf(
    const __half* __restrict__ A, const __half* __restrict__ Wt,
    const float* __restrict__ bias, const float* __restrict__ res,
    void* __restrict__ Cv, int M, int N, int K)
{
    const int MI = 2, NI = 8;            // WM=32, WN=64
    const int RS = 144;
    const int A_BYTES = 128 * RS;
    const int B_BYTES = 128 * RS;

    extern __shared__ char sm[];
    char* Asm = sm;
    char* Bsm = sm + 2 * A_BYTES;

    int tid = threadIdx.x;
    int bx = blockIdx.x, by = blockIdx.y;
    int wid = tid >> 5, lane = tid & 31;
    int wn = wid & 1, wm = wid >> 1;
    int g = lane >> 2, q = lane & 3;

    const __half* Ab = A  + (size_t)by * 128 * K;
    const __half* Bb = Wt + (size_t)bx * 128 * K;
    int KT = K / 64;

    float acc[MI][NI][4];
#pragma unroll
    for (int mi = 0; mi < MI; mi++)
#pragma unroll
        for (int ni = 0; ni < NI; ni++)
#pragma unroll
            for (int k = 0; k < 4; k++) acc[mi][ni][k] = 0.f;

    auto load_tile = [&](int kt, int s) {
#pragma unroll
        for (int i = 0; i < 4; i++) {
            int idx = tid + i * 256;
            int r = idx >> 3, c = idx & 7;
            cp16(Asm + s * A_BYTES + r * RS + c * 16,
                 Ab + (size_t)r * K + kt * 64 + c * 8);
        }
#pragma unroll
        for (int i = 0; i < 4; i++) {
            int idx = tid + i * 256;
            int r = idx >> 3, c = idx & 7;
            cp16(Bsm + s * B_BYTES + r * RS + c * 16,
                 Bb + (size_t)r * K + kt * 64 + c * 8);
        }
        cp_commit();
    };

    load_tile(0, 0);

    for (int kt = 0; kt < KT; kt++) {
        int s = kt & 1;
        if (kt + 1 < KT) {
            load_tile(kt + 1, (kt + 1) & 1);
            asm volatile("cp.async.wait_group 1;");
        } else {
            asm volatile("cp.async.wait_group 0;");
        }
        __syncthreads();
        const char* As = Asm + s * A_BYTES;
        const char* Bs = Bsm + s * B_BYTES;
#pragma unroll
        for (int ks = 0; ks < 4; ks++) {
            int kb = ks * 32;
            uint32_t a[MI][4];
#pragma unroll
            for (int mi = 0; mi < MI; mi++) {
                const char* p0 = As + (wm * 32 + mi * 16 + g) * RS + kb + 4 * q;
                const char* p1 = As + (wm * 32 + mi * 16 + 8 + g) * RS + kb + 4 * q;
                a[mi][0] = *(const uint32_t*)(p0);
                a[mi][1] = *(const uint32_t*)(p1);
                a[mi][2] = *(const uint32_t*)(p0 + 16);
                a[mi][3] = *(const uint32_t*)(p1 + 16);
            }
            uint32_t b[NI][2];
#pragma unroll
            for (int ni = 0; ni < NI; ni++) {
                const char* pb = Bs + (wn * 64 + ni * 8 + g) * RS + kb + 4 * q;
                b[ni][0] = *(const uint32_t*)(pb);
                b[ni][1] = *(const uint32_t*)(pb + 16);
            }
#pragma unroll
            for (int mi = 0; mi < MI; mi++)
#pragma unroll
                for (int ni = 0; ni < NI; ni++) mma16(acc[mi][ni], a[mi], b[ni]);
        }
        __syncthreads();
    }

#pragma unroll
    for (int mi = 0; mi < MI; mi++) {
        int r0 = by * 128 + wm * 32 + mi * 16 + g;
#pragma unroll
        for (int ni = 0; ni < NI; ni++) {
            int c = bx * 128 + wn * 64 + ni * 8 + q * 2;
            float2 v0 = make_float2(acc[mi][ni][0], acc[mi][ni][1]);
            float2 v1 = make_float2(acc[mi][ni][2], acc[mi][ni][3]);
            if (EPI & 1) {
                float b0 = bias[c], b1 = bias[c + 1];
                v0.x += b0; v0.y += b1; v1.x += b0; v1.y += b1;
            }
            if (EPI & 2) {
                const float is2 = 0.70710678118654752f;
                v0.x = 0.5f * v0.x * (1.f + erff(v0.x * is2));
                v0.y = 0.5f * v0.y * (1.f + erff(v0.y * is2));
                v1.x = 0.5f * v1.x * (1.f + erff(v1.x * is2));
                v1.y = 0.5f * v1.y * (1.f + erff(v1.y * is2));
            }
            size_t a0 = (size_t)r0 * N + c;
            size_t a1 = (size_t)(r0 + 8) * N + c;
            if (EPI & 4) {
                float2 r0v = *(const float2*)(res + a0);
                float2 r1v = *(const float2*)(res + a1);
                v0.x += r0v.x; v0.y += r0v.y; v1.x += r1v.x; v1.y += r1v.y;
            }
            if (OH) {
                __half* C = (__half*)Cv;
                *(__half2*)(C + a0) = __floats2half2_rn(v0.x, v0.y);
                *(__half2*)(C + a1) = __floats2half2_rn(v1.x, v1.y);
            } else {
                float* C = (float*)Cv;
                *(float2*)(C + a0) = v0;
                *(float2*)(C + a1) = v1;
            }
        }
    }
}

// ---------------- attention scores (fp16 mma): S = Q K^T * scale -----------
__global__ void __launch_bounds__(256, 2) scores_hf(
    const __half* __restrict__ qkv, __half* __restrict__ attn)
{
    const int RS = 144;
    extern __shared__ char sm[];
    char* Qs = sm;
    char* Ks = sm + 128 * RS;

    int bh = blockIdx.z;
    int b = bh >> 4, h = bh & 15;
    int i0 = blockIdx.y * 128, j0 = blockIdx.x * 128;
    const __half* Qb = qkv + (size_t)b * N_ * 3 * D_ + (size_t)h * DH_;
    const __half* Kb = Qb + D_;

    int tid = threadIdx.x;
    int wid = tid >> 5, lane = tid & 31;
    int wm = wid >> 1, wn = wid & 1;      // WM=32, WN=64
    int g = lane >> 2, q = lane & 3;

#pragma unroll
    for (int i = 0; i < 4; i++) {
        int idx = tid + i * 256;
        int r = idx >> 3, c = idx & 7;
        cp16(Qs + r * RS + c * 16, Qb + (size_t)(i0 + r) * 3 * D_ + c * 8);
        cp16(Ks + r * RS + c * 16, Kb + (size_t)(j0 + r) * 3 * D_ + c * 8);
    }
    cp_commit();
    asm volatile("cp.async.wait_group 0;");
    __syncthreads();

    float acc[2][8][4];
#pragma unroll
    for (int mi = 0; mi < 2; mi++)
#pragma unroll
        for (int ni = 0; ni < 8; ni++)
#pragma unroll
            for (int k = 0; k < 4; k++) acc[mi][ni][k] = 0.f;

#pragma unroll
    for (int ks = 0; ks < 4; ks++) {
        int kb = ks * 32;
        uint32_t a[2][4];
#pragma unroll
        for (int mi = 0; mi < 2; mi++) {
            const char* p0 = Qs + (wm * 32 + mi * 16 + g) * RS + kb + 4 * q;
            const char* p1 = Qs + (wm * 32 + mi * 16 + 8 + g) * RS + kb + 4 * q;
            a[mi][0] = *(const uint32_t*)(p0);
            a[mi][1] = *(const uint32_t*)(p1);
            a[mi][2] = *(const uint32_t*)(p0 + 16);
            a[mi][3] = *(const uint32_t*)(p1 + 16);
        }
        uint32_t br[8][2];
#pragma unroll
        for (int ni = 0; ni < 8; ni++) {
            const char* pb = Ks + (wn * 64 + ni * 8 + g) * RS + kb + 4 * q;
            br[ni][0] = *(const uint32_t*)(pb);
            br[ni][1] = *(const uint32_t*)(pb + 16);
        }
#pragma unroll
        for (int mi = 0; mi < 2; mi++)
#pragma unroll
            for (int ni = 0; ni < 8; ni++) mma16(acc[mi][ni], a[mi], br[ni]);
    }

    const float scale = 0.03125f;   // D^-0.5 (full-dim per reference)
    __half* Ao = attn + (size_t)bh * N_ * N_;
#pragma unroll
    for (int mi = 0; mi < 2; mi++) {
        int r0 = i0 + wm * 32 + mi * 16 + g;
#pragma unroll
        for (int ni = 0; ni < 8; ni++) {
            int c = j0 + wn * 64 + ni * 8 + q * 2;
            *(__half2*)(Ao + (size_t)r0 * N_ + c) =
                __floats2half2_rn(acc[mi][ni][0] * scale, acc[mi][ni][1] * scale);
            *(__half2*)(Ao + (size_t)(r0 + 8) * N_ + c) =
                __floats2half2_rn(acc[mi][ni][2] * scale, acc[mi][ni][3] * scale);
        }
    }
}

// ---------------- row softmax over N=1024 (fp16 storage) --------------------
__global__ void __launch_bounds__(256) softmax_hf(__half* __restrict__ attn)
{
    __shared__ float red[8];
    size_t row = blockIdx.x;
    __half* p = attn + row * N_;
    int t = threadIdx.x;
    float v[4];
    float mx = -1e30f;
#pragma unroll
    for (int i = 0; i < 4; i++) {
        v[i] = __half2float(p[t + i * 256]);
        mx = fmaxf(mx, v[i]);
    }
#pragma unroll
    for (int off = 16; off > 0; off >>= 1)
        mx = fmaxf(mx, __shfl_xor_sync(0xffffffffu, mx, off));
    if ((t & 31) == 0) red[t >> 5] = mx;
    __syncthreads();
    mx = red[0];
#pragma unroll
    for (int i = 1; i < 8; i++) mx = fmaxf(mx, red[i]);
    __syncthreads();
    float sum = 0.f;
#pragma unroll
    for (int i = 0; i < 4; i++) { v[i] = __expf(v[i] - mx); sum += v[i]; }
#pragma unroll
    for (int off = 16; off > 0; off >>= 1)
        sum += __shfl_xor_sync(0xffffffffu, sum, off);
    if ((t & 31) == 0) red[t >> 5] = sum;
    __syncthreads();
    sum = 0.f;
#pragma unroll
    for (int i = 0; i < 8; i++) sum += red[i];
    float inv = 1.f / sum;
#pragma unroll
    for (int i = 0; i < 4; i++) p[t + i * 256] = __float2half_rn(v[i] * inv);
}

// ---------------- O = attn @ Vt^T (fp16 mma), output fp16 -------------------
__global__ void __launch_bounds__(256, 2) av_hf(
    const __half* __restrict__ attn, const __half* __restrict__ vt,
    __half* __restrict__ o)
{
    const int RS = 144;
    const int A_BYTES = 128 * RS;
    const int B_BYTES = 64 * RS;
    extern __shared__ char sm[];
    char* Asm = sm;
    char* Bsm = sm + 2 * A_BYTES;

    int bh = blockIdx.y;
    int b = bh >> 4, h = bh & 15;
    int i0 = blockIdx.x * 128;
    const __half* Ab = attn + (size_t)bh * N_ * N_ + (size_t)i0 * N_;
    const __half* Bb = vt + (size_t)bh * DH_ * N_;

    int tid = threadIdx.x;
    int wid = tid >> 5, lane = tid & 31;
    int wm = wid >> 1, wn = wid & 1;      // WM=32, WN=32
    int g = lane >> 2, q = lane & 3;

    float acc[2][4][4];
#pragma unroll
    for (int mi = 0; mi < 2; mi++)
#pragma unroll
        for (int ni = 0; ni < 4; ni++)
#pragma unroll
            for (int k = 0; k < 4; k++) acc[mi][ni][k] = 0.f;

    auto load_tile = [&](int kt, int s) {
#pragma unroll
        for (int i = 0; i < 4; i++) {
            int idx = tid + i * 256;
            int r = idx >> 3, c = idx & 7;
            cp16(Asm + s * A_BYTES + r * RS + c * 16,
                 Ab + (size_t)r * N_ + kt * 64 + c * 8);
        }
#pragma unroll
        for (int i = 0; i < 2; i++) {
            int idx = tid + i * 256;
            int r = idx >> 3, c = idx & 7;
            cp16(Bsm + s * B_BYTES + r * RS + c * 16,
                 Bb + (size_t)r * N_ + kt * 64 + c * 8);
        }
        cp_commit();
    };

    load_tile(0, 0);

    for (int kt = 0; kt < 16; kt++) {
        int s = kt & 1;
        if (kt + 1 < 16) {
            load_tile(kt + 1, (kt + 1) & 1);
            asm volatile("cp.async.wait_group 1;");
        } else {
            asm volatile("cp.async.wait_group 0;");
        }
        __syncthreads();
        const char* As = Asm + s * A_BYTES;
        const char* Bs = Bsm + s * B_BYTES;
#pragma unroll
        for (int ks = 0; ks < 4; ks++) {
            int kb = ks * 32;
            uint32_t a[2][4];
#pragma unroll
            for (int mi = 0; mi < 2; mi++) {
                const char* p0 = As + (wm * 32 + mi * 16 + g) * RS + kb + 4 * q;
                const char* p1 = As + (wm * 32 + mi * 16 + 8 + g) * RS + kb + 4 * q;
                a[mi][0] = *(const uint32_t*)(p0);
                a[mi][1] = *(const uint32_t*)(p1);
                a[mi][2] = *(const uint32_t*)(p0 + 16);
                a[mi][3] = *(const uint32_t*)(p1 + 16);
            }
            uint32_t br[4][2];
#pragma unroll
            for (int ni = 0; ni < 4; ni++) {
                const char* pb = Bs + (wn * 32 + ni * 8 + g) * RS + kb + 4 * q;
                br[ni][0] = *(const uint32_t*)(pb);
                br[ni][1] = *(const uint32_t*)(pb + 16);
            }
#pragma unroll
            for (int mi = 0; mi < 2; mi++)
#pragma unroll
                for (int ni = 0; ni < 4; ni++) mma16(acc[mi][ni], a[mi], br[ni]);
        }
        __syncthreads();
    }

#pragma unroll
    for (int mi = 0; mi < 2; mi++) {
        int r0 = i0 + wm * 32 + mi * 16 + g;
#pragma unroll
        for (int ni = 0; ni < 4; ni++) {
            int c = h * DH_ + wn * 32 + ni * 8 + q * 2;
            size_t a0 = ((size_t)b * N_ + r0) * D_ + c;
            size_t a1 = ((size_t)b * N_ + r0 + 8) * D_ + c;
            *(__half2*)(o + a0) = __floats2half2_rn(acc[mi][ni][0], acc[mi][ni][1]);
            *(__half2*)(o + a1) = __floats2half2_rn(acc[mi][ni][2], acc[mi][ni][3]);
        }
    }
}

// ---------------- orchestration --------------------------------------------
#define HF_SMEM   (2 * (128 * 144) + 2 * (128 * 144))   /* 73728 -> 2 CTAs/SM */
#define SC_SMEM   (2 * (128 * 144))                     /* 36864 */
#define AV_SMEM   (2 * (128 * 144) + 2 * (64 * 144))    /* 55296 */

extern "C" void kernel_launch(void* const* d_in, const int* in_sizes, int n_in,
                              void* d_out, int out_size)
{
    (void)in_sizes; (void)n_in; (void)out_size;
    const float* x     = (const float*)d_in[0];
    const float* ln1_s = (const float*)d_in[1];
    const float* ln1_b = (const float*)d_in[2];
    const float* w_qkv = (const float*)d_in[3];
    const float* w_out = (const float*)d_in[4];
    const float* b_out = (const float*)d_in[5];
    const float* ln2_s = (const float*)d_in[6];
    const float* ln2_b = (const float*)d_in[7];
    const float* w1    = (const float*)d_in[8];
    const float* b1    = (const float*)d_in[9];
    const float* w2    = (const float*)d_in[10];
    const float* b2    = (const float*)d_in[11];
    float* out = (float*)d_out;

    __half *h, *qkv, *attn, *vt, *o, *mlp, *wqkv, *wout, *w1t, *w2t;
    cudaGetSymbolAddress((void**)&h,    g_h);
    cudaGetSymbolAddress((void**)&qkv,  g_qkv);
    cudaGetSymbolAddress((void**)&attn, g_attn);
    cudaGetSymbolAddress((void**)&vt,   g_vt);
    cudaGetSymbolAddress((void**)&o,    g_o);
    cudaGetSymbolAddress((void**)&mlp,  g_mlp);
    cudaGetSymbolAddress((void**)&wqkv, g_wqkv);
    cudaGetSymbolAddress((void**)&wout, g_wout);
    cudaGetSymbolAddress((void**)&w1t,  g_w1);
    cudaGetSymbolAddress((void**)&w2t,  g_w2);

    cudaFuncSetAttribute(gemm_hf<0, 1>,
        cudaFuncAttributeMaxDynamicSharedMemorySize, HF_SMEM);
    cudaFuncSetAttribute(gemm_hf<3, 1>,
        cudaFuncAttributeMaxDynamicSharedMemorySize, HF_SMEM);
    cudaFuncSetAttribute(gemm_hf<5, 0>,
        cudaFuncAttributeMaxDynamicSharedMemorySize, HF_SMEM);
    cudaFuncSetAttribute(scores_hf,
        cudaFuncAttributeMaxDynamicSharedMemorySize, SC_SMEM);
    cudaFuncSetAttribute(av_hf,
        cudaFuncAttributeMaxDynamicSharedMemorySize, AV_SMEM);

    // pre-pass: weights -> [N][K] fp16
    wtrans_kernel<<<dim3(3 * D_ / 32, D_ / 32, DEPTH_), 256>>>(w_qkv, wqkv, D_, 3 * D_);
    wtrans_kernel<<<dim3(D_ / 32, D_ / 32, DEPTH_), 256>>>(w_out, wout, D_, D_);
    wtrans_kernel<<<dim3(MLP_ / 32, D_ / 32, DEPTH_), 256>>>(w1, w1t, D_, MLP_);
    wtrans_kernel<<<dim3(D_ / 32, MLP_ / 32, DEPTH_), 256>>>(w2, w2t, MLP_, D_);

    cudaMemcpyAsync(out, x, (size_t)M_ * D_ * sizeof(float),
                    cudaMemcpyDeviceToDevice);

    for (int l = 0; l < DEPTH_; l++) {
        // --- attention block ---
        ln_kernel<<<M_, 256>>>(out, ln1_s + (size_t)l * D_, ln1_b + (size_t)l * D_, h);
        gemm_hf<0, 1><<<dim3(3 * D_ / 128, M_ / 128), 256, HF_SMEM>>>(
            h, wqkv + (size_t)l * D_ * 3 * D_, nullptr, nullptr,
            qkv, M_, 3 * D_, D_);
        vtrans_kernel<<<dim3(N_ / 64, B_ * H_), 256>>>(qkv, vt);
        scores_hf<<<dim3(8, 8, B_ * H_), 256, SC_SMEM>>>(qkv, attn);
        softmax_hf<<<B_ * H_ * N_, 256>>>(attn);
        av_hf<<<dim3(N_ / 128, B_ * H_), 256, AV_SMEM>>>(attn, vt, o);
        gemm_hf<5, 0><<<dim3(D_ / 128, M_ / 128), 256, HF_SMEM>>>(
            o, wout + (size_t)l * D_ * D_, b_out + (size_t)l * D_,
            out, out, M_, D_, D_);
        // --- MLP block ---
        ln_kernel<<<M_, 256>>>(out, ln2_s + (size_t)l * D_, ln2_b + (size_t)l * D_, h);
        gemm_hf<3, 1><<<dim3(MLP_ / 128, M_ / 128), 256, HF_SMEM>>>(
            h, w1t + (size_t)l * D_ * MLP_, b1 + (size_t)l * MLP_,
            nullptr, mlp, M_, MLP_, D_);
        gemm_hf<5, 0><<<dim3(D_ / 128, M_ / 128), 256, HF_SMEM>>>(
            mlp, w2t + (size_t)l * MLP_ * D_, b2 + (size_t)l * D_,
            out, out, M_, D_, MLP_);
    }
}

// round 12
// speedup vs baseline: 1.2563x; 1.1681x over previous
#include <cuda_runtime.h>
#include <cuda_fp16.h>
#include <math.h>
#include <stdint.h>

#define B_    2
#define N_    1024
#define D_    1024
#define H_    16
#define DH_   64
#define MLP_  4096
#define DEPTH_ 6
#define M_    (B_ * N_)   /* 2048 rows */

// ---------------- scratch -----------------------------------------------
__device__ __half g_h  [(size_t)M_ * D_];
__device__ __half g_qkv[(size_t)M_ * 3 * D_];
__device__ __half g_vt [(size_t)B_ * H_ * DH_ * N_];
__device__ __half g_o  [(size_t)M_ * D_];
__device__ __half g_mlp[(size_t)M_ * MLP_];
__device__ __half g_wqkv[(size_t)DEPTH_ * D_ * 3 * D_];
__device__ __half g_wout[(size_t)DEPTH_ * D_ * D_];
__device__ __half g_w1  [(size_t)DEPTH_ * D_ * MLP_];
__device__ __half g_w2  [(size_t)DEPTH_ * MLP_ * D_];

// ---------------- helpers ---------------------------------------------------
__device__ __forceinline__ void mma16(float* d, const uint32_t* a, const uint32_t* b) {
    asm volatile(
        "mma.sync.aligned.m16n8k16.row.col.f32.f16.f16.f32 "
        "{%0,%1,%2,%3},{%4,%5,%6,%7},{%8,%9},{%0,%1,%2,%3};"
        : "+f"(d[0]), "+f"(d[1]), "+f"(d[2]), "+f"(d[3])
        : "r"(a[0]), "r"(a[1]), "r"(a[2]), "r"(a[3]),
          "r"(b[0]), "r"(b[1]));
}
__device__ __forceinline__ void cp16(void* smem_dst, const void* gmem_src) {
    uint32_t dst = (uint32_t)__cvta_generic_to_shared(smem_dst);
    asm volatile("cp.async.cg.shared.global [%0], [%1], 16;"
                 :: "r"(dst), "l"(gmem_src));
}
__device__ __forceinline__ void cp_commit() {
    asm volatile("cp.async.commit_group;");
}

// ---------------- weight pre-pass: [K,N] fp32 -> [N,K] fp16 -----------------
__global__ void __launch_bounds__(256) wtrans_kernel(
    const float* __restrict__ src, __half* __restrict__ dst, int K, int N)
{
    __shared__ float t[32][33];
    int n0 = blockIdx.x * 32, k0 = blockIdx.y * 32;
    src += (size_t)blockIdx.z * K * N;
    dst += (size_t)blockIdx.z * K * N;
    int tx = threadIdx.x & 31, ty = threadIdx.x >> 5;
#pragma unroll
    for (int i = ty; i < 32; i += 8)
        t[i][tx] = src[(size_t)(k0 + i) * N + n0 + tx];
    __syncthreads();
#pragma unroll
    for (int i = ty; i < 32; i += 8)
        dst[(size_t)(n0 + i) * K + k0 + tx] = __float2half_rn(t[tx][i]);
}

// ---------------- V transpose: qkv fp16 -> Vt[bh][d][j] ---------------------
__global__ void __launch_bounds__(256) vtrans_kernel(
    const __half* __restrict__ qkv, __half* __restrict__ vt)
{
    __shared__ __half t[64][66];
    int bh = blockIdx.y;
    int b = bh >> 4, h = bh & 15;
    int j0 = blockIdx.x * 64;
    const __half* src = qkv + (size_t)b * N_ * 3 * D_ + 2 * D_ + (size_t)h * DH_;
    __half* dst = vt + (size_t)bh * DH_ * N_;
    int tid = threadIdx.x;
#pragma unroll
    for (int i = 0; i < 16; i++) {
        int idx = tid + i * 256;
        int j = idx >> 6, d = idx & 63;
        t[j][d] = src[(size_t)(j0 + j) * 3 * D_ + d];
    }
    __syncthreads();
#pragma unroll
    for (int i = 0; i < 16; i++) {
        int idx = tid + i * 256;
        int d = idx >> 6, j = idx & 63;
        dst[(size_t)d * N_ + j0 + j] = t[j][d];
    }
}

// ---------------- LayerNorm (emits fp16) -----------------------------------
__global__ void __launch_bounds__(256) ln_kernel(
    const float* __restrict__ x, const float* __restrict__ s,
    const float* __restrict__ b, __half* __restrict__ o)
{
    __shared__ float red[2][8];
    int row = blockIdx.x;
    const float* xr = x + (size_t)row * D_;
    __half* orow = o + (size_t)row * D_;
    int t = threadIdx.x;
    float v[4];
    float sum = 0.f, sq = 0.f;
#pragma unroll
    for (int i = 0; i < 4; i++) {
        float z = xr[t + i * 256];
        v[i] = z; sum += z; sq += z * z;
    }
#pragma unroll
    for (int off = 16; off > 0; off >>= 1) {
        sum += __shfl_xor_sync(0xffffffffu, sum, off);
        sq  += __shfl_xor_sync(0xffffffffu, sq,  off);
    }
    if ((t & 31) == 0) { red[0][t >> 5] = sum; red[1][t >> 5] = sq; }
    __syncthreads();
    sum = 0.f; sq = 0.f;
#pragma unroll
    for (int i = 0; i < 8; i++) { sum += red[0][i]; sq += red[1][i]; }
    float mean = sum * (1.f / D_);
    float var  = sq  * (1.f / D_) - mean * mean;
    float rstd = rsqrtf(var + 1e-5f);
#pragma unroll
    for (int i = 0; i < 4; i++) {
        int c = t + i * 256;
        orow[c] = __float2half_rn((v[i] - mean) * rstd * s[c] + b[c]);
    }
}

// ---------------- fp16 tensor-core GEMM, cp.async, 2 CTAs/SM ----------------
template<int EPI, int OH>
__global__ void __launch_bounds__(256, 2) gemm_hf(
    const __half* __restrict__ A, const __half* __restrict__ Wt,
    const float* __restrict__ bias, const float* __restrict__ res,
    void* __restrict__ Cv, int M, int N, int K)
{
    const int MI = 2, NI = 8;            // WM=32, WN=64
    const int RS = 144;
    const int A_BYTES = 128 * RS;
    const int B_BYTES = 128 * RS;

    extern __shared__ char sm[];
    char* Asm = sm;
    char* Bsm = sm + 2 * A_BYTES;

    int tid = threadIdx.x;
    int bx = blockIdx.x, by = blockIdx.y;
    int wid = tid >> 5, lane = tid & 31;
    int wn = wid & 1, wm = wid >> 1;
    int g = lane >> 2, q = lane & 3;

    const __half* Ab = A  + (size_t)by * 128 * K;
    const __half* Bb = Wt + (size_t)bx * 128 * K;
    int KT = K / 64;

    float acc[MI][NI][4];
#pragma unroll
    for (int mi = 0; mi < MI; mi++)
#pragma unroll
        for (int ni = 0; ni < NI; ni++)
#pragma unroll
            for (int k = 0; k < 4; k++) acc[mi][ni][k] = 0.f;

    auto load_tile = [&](int kt, int s) {
#pragma unroll
        for (int i = 0; i < 4; i++) {
            int idx = tid + i * 256;
            int r = idx >> 3, c = idx & 7;
            cp16(Asm + s * A_BYTES + r * RS + c * 16,
                 Ab + (size_t)r * K + kt * 64 + c * 8);
        }
#pragma unroll
        for (int i = 0; i < 4; i++) {
            int idx = tid + i * 256;
            int r = idx >> 3, c = idx & 7;
            cp16(Bsm + s * B_BYTES + r * RS + c * 16,
                 Bb + (size_t)r * K + kt * 64 + c * 8);
        }
        cp_commit();
    };

    load_tile(0, 0);

    for (int kt = 0; kt < KT; kt++) {
        int s = kt & 1;
        if (kt + 1 < KT) {
            load_tile(kt + 1, (kt + 1) & 1);
            asm volatile("cp.async.wait_group 1;");
        } else {
            asm volatile("cp.async.wait_group 0;");
        }
        __syncthreads();
        const char* As = Asm + s * A_BYTES;
        const char* Bs = Bsm + s * B_BYTES;
#pragma unroll
        for (int ks = 0; ks < 4; ks++) {
            int kb = ks * 32;
            uint32_t a[MI][4];
#pragma unroll
            for (int mi = 0; mi < MI; mi++) {
                const char* p0 = As + (wm * 32 + mi * 16 + g) * RS + kb + 4 * q;
                const char* p1 = As + (wm * 32 + mi * 16 + 8 + g) * RS + kb + 4 * q;
                a[mi][0] = *(const uint32_t*)(p0);
                a[mi][1] = *(const uint32_t*)(p1);
                a[mi][2] = *(const uint32_t*)(p0 + 16);
                a[mi][3] = *(const uint32_t*)(p1 + 16);
            }
            uint32_t b[NI][2];
#pragma unroll
            for (int ni = 0; ni < NI; ni++) {
                const char* pb = Bs + (wn * 64 + ni * 8 + g) * RS + kb + 4 * q;
                b[ni][0] = *(const uint32_t*)(pb);
                b[ni][1] = *(const uint32_t*)(pb + 16);
            }
#pragma unroll
            for (int mi = 0; mi < MI; mi++)
#pragma unroll
                for (int ni = 0; ni < NI; ni++) mma16(acc[mi][ni], a[mi], b[ni]);
        }
        __syncthreads();
    }

#pragma unroll
    for (int mi = 0; mi < MI; mi++) {
        int r0 = by * 128 + wm * 32 + mi * 16 + g;
#pragma unroll
        for (int ni = 0; ni < NI; ni++) {
            int c = bx * 128 + wn * 64 + ni * 8 + q * 2;
            float2 v0 = make_float2(acc[mi][ni][0], acc[mi][ni][1]);
            float2 v1 = make_float2(acc[mi][ni][2], acc[mi][ni][3]);
            if (EPI & 1) {
                float b0 = bias[c], b1 = bias[c + 1];
                v0.x += b0; v0.y += b1; v1.x += b0; v1.y += b1;
            }
            if (EPI & 2) {
                const float is2 = 0.70710678118654752f;
                v0.x = 0.5f * v0.x * (1.f + erff(v0.x * is2));
                v0.y = 0.5f * v0.y * (1.f + erff(v0.y * is2));
                v1.x = 0.5f * v1.x * (1.f + erff(v1.x * is2));
                v1.y = 0.5f * v1.y * (1.f + erff(v1.y * is2));
            }
            size_t a0 = (size_t)r0 * N + c;
            size_t a1 = (size_t)(r0 + 8) * N + c;
            if (EPI & 4) {
                float2 r0v = *(const float2*)(res + a0);
                float2 r1v = *(const float2*)(res + a1);
                v0.x += r0v.x; v0.y += r0v.y; v1.x += r1v.x; v1.y += r1v.y;
            }
            if (OH) {
                __half* C = (__half*)Cv;
                *(__half2*)(C + a0) = __floats2half2_rn(v0.x, v0.y);
                *(__half2*)(C + a1) = __floats2half2_rn(v1.x, v1.y);
            } else {
                float* C = (float*)Cv;
                *(float2*)(C + a0) = v0;
                *(float2*)(C + a1) = v1;
            }
        }
    }
}

// ---------------- fused flash attention (fp16) ------------------------------
// grid (N/128 = 8, B*H = 32), 256 thr = 8 warps; warp w owns q-rows w*16..+15.
// Q tile resident; K and Vt chunks of 64 double-buffered via cp.async.
// Online softmax warp-local (rows g, 8+g; quad shfl reductions).
// smem: Q 18K | K 2x9K | Vt 2x9K | P 8x2.25K  = 72KB -> 2 CTAs/SM.
#define FL_RS    144
#define FL_Q     0
#define FL_K     (128 * FL_RS)
#define FL_V     (FL_K + 2 * 64 * FL_RS)
#define FL_P     (FL_V + 2 * 64 * FL_RS)
#define FL_SMEM  (FL_P + 8 * 16 * FL_RS)    /* 73728 */

__global__ void __launch_bounds__(256, 2) flash_hf(
    const __half* __restrict__ qkv, const __half* __restrict__ vt,
    __half* __restrict__ o)
{
    const int RS = FL_RS;
    extern __shared__ char sm[];
    char* Qs = sm + FL_Q;
    char* Ks = sm + FL_K;
    char* Vs = sm + FL_V;

    int bh = blockIdx.y;
    int b = bh >> 4, h = bh & 15;
    int i0 = blockIdx.x * 128;
    const __half* Qb  = qkv + (size_t)b * N_ * 3 * D_ + (size_t)h * DH_;
    const __half* Kb  = Qb + D_;
    const __half* Vtb = vt + (size_t)bh * DH_ * N_;

    int tid = threadIdx.x, wid = tid >> 5, lane = tid & 31;
    int g = lane >> 2, q = lane & 3;
    char* Pw = sm + FL_P + wid * 16 * RS;   // warp-private P slab (16x64 fp16)

    // Q tile (128 x 64), group A
#pragma unroll
    for (int i = 0; i < 4; i++) {
        int idx = tid + i * 256;
        int r = idx >> 3, c = idx & 7;
        cp16(Qs + r * RS + c * 16, Qb + (size_t)(i0 + r) * 3 * D_ + c * 8);
    }
    cp_commit();

    auto load_kv = [&](int kt, int s) {
        int j0 = kt * 64;
#pragma unroll
        for (int i = 0; i < 2; i++) {
            int idx = tid + i * 256;
            int r = idx >> 3, c = idx & 7;                 // r: 0..63
            cp16(Ks + s * 64 * RS + r * RS + c * 16,
                 Kb + (size_t)(j0 + r) * 3 * D_ + c * 8);  // K rows j
            cp16(Vs + s * 64 * RS + r * RS + c * 16,
                 Vtb + (size_t)r * N_ + j0 + c * 8);       // Vt rows d
        }
        cp_commit();
    };

    load_kv(0, 0);

    float oacc[8][4];
#pragma unroll
    for (int ni = 0; ni < 8; ni++)
#pragma unroll
        for (int k = 0; k < 4; k++) oacc[ni][k] = 0.f;
    float mr0 = -1e30f, mr1 = -1e30f, lr0 = 0.f, lr1 = 0.f;

    const float scale = 0.03125f;   // D^-0.5 (full-dim per reference)
    char* Qw = Qs + wid * 16 * RS;  // this warp's 16 Q rows

    for (int kt = 0; kt < 16; kt++) {
        int s = kt & 1;
        if (kt + 1 < 16) {
            load_kv(kt + 1, (kt + 1) & 1);
            asm volatile("cp.async.wait_group 1;");
        } else {
            asm volatile("cp.async.wait_group 0;");
        }
        __syncthreads();
        const char* Kc = Ks + s * 64 * RS;
        const char* Vc = Vs + s * 64 * RS;

        // ---- S = Q K^T (warp: 16 x 64) ----
        float sacc[8][4];
#pragma unroll
        for (int ni = 0; ni < 8; ni++)
#pragma unroll
            for (int k = 0; k < 4; k++) sacc[ni][k] = 0.f;
#pragma unroll
        for (int ks = 0; ks < 4; ks++) {
            int kb = ks * 32;
            uint32_t a[4];
            const char* p0 = Qw + g * RS + kb + 4 * q;
            const char* p1 = Qw + (8 + g) * RS + kb + 4 * q;
            a[0] = *(const uint32_t*)(p0);
            a[1] = *(const uint32_t*)(p1);
            a[2] = *(const uint32_t*)(p0 + 16);
            a[3] = *(const uint32_t*)(p1 + 16);
#pragma unroll
            for (int ni = 0; ni < 8; ni++) {
                uint32_t b2[2];
                const char* pb = Kc + (ni * 8 + g) * RS + kb + 4 * q;
                b2[0] = *(const uint32_t*)(pb);
                b2[1] = *(const uint32_t*)(pb + 16);
                mma16(sacc[ni], a, b2);
            }
        }

        // ---- online softmax (rows g and 8+g of this warp) ----
        float mx0 = -1e30f, mx1 = -1e30f;
#pragma unroll
        for (int ni = 0; ni < 8; ni++) {
            sacc[ni][0] *= scale; sacc[ni][1] *= scale;
            sacc[ni][2] *= scale; sacc[ni][3] *= scale;
            mx0 = fmaxf(mx0, fmaxf(sacc[ni][0], sacc[ni][1]));
            mx1 = fmaxf(mx1, fmaxf(sacc[ni][2], sacc[ni][3]));
        }
        mx0 = fmaxf(mx0, __shfl_xor_sync(0xffffffffu, mx0, 1));
        mx0 = fmaxf(mx0, __shfl_xor_sync(0xffffffffu, mx0, 2));
        mx1 = fmaxf(mx1, __shfl_xor_sync(0xffffffffu, mx1, 1));
        mx1 = fmaxf(mx1, __shfl_xor_sync(0xffffffffu, mx1, 2));
        float mn0 = fmaxf(mr0, mx0), mn1 = fmaxf(mr1, mx1);
        float corr0 = __expf(mr0 - mn0), corr1 = __expf(mr1 - mn1);
        mr0 = mn0; mr1 = mn1;

        float ls0 = 0.f, ls1 = 0.f;
#pragma unroll
        for (int ni = 0; ni < 8; ni++) {
            float p0 = __expf(sacc[ni][0] - mn0);
            float p1 = __expf(sacc[ni][1] - mn0);
            float p2 = __expf(sacc[ni][2] - mn1);
            float p3 = __expf(sacc[ni][3] - mn1);
            ls0 += p0 + p1; ls1 += p2 + p3;
            int cb = ni * 16 + 4 * q;   // byte offset of cols ni*8+2q
            *(__half2*)(Pw + g * RS + cb)       = __floats2half2_rn(p0, p1);
            *(__half2*)(Pw + (8 + g) * RS + cb) = __floats2half2_rn(p2, p3);
        }
        lr0 = lr0 * corr0 + ls0;
        lr1 = lr1 * corr1 + ls1;
#pragma unroll
        for (int ni = 0; ni < 8; ni++) {
            oacc[ni][0] *= corr0; oacc[ni][1] *= corr0;
            oacc[ni][2] *= corr1; oacc[ni][3] *= corr1;
        }
        __syncwarp();

        // ---- O += P * Vt (warp: 16 x 64, k = 64) ----
#pragma unroll
        for (int ks = 0; ks < 4; ks++) {
            int kb = ks * 32;
            uint32_t a[4];
            const char* p0 = Pw + g * RS + kb + 4 * q;
            const char* p1 = Pw + (8 + g) * RS + kb + 4 * q;
            a[0] = *(const uint32_t*)(p0);
            a[1] = *(const uint32_t*)(p1);
            a[2] = *(const uint32_t*)(p0 + 16);
            a[3] = *(const uint32_t*)(p1 + 16);
#pragma unroll
            for (int ni = 0; ni < 8; ni++) {
                uint32_t b2[2];
                const char* pb = Vc + (ni * 8 + g) * RS + kb + 4 * q;
                b2[0] = *(const uint32_t*)(pb);
                b2[1] = *(const uint32_t*)(pb + 16);
                mma16(oacc[ni], a, b2);
            }
        }
        __syncthreads();   // all warps done with K/V buffer s before reuse
    }

    // finalize: quad-reduce row sums, normalize, write
    lr0 += __shfl_xor_sync(0xffffffffu, lr0, 1);
    lr0 += __shfl_xor_sync(0xffffffffu, lr0, 2);
    lr1 += __shfl_xor_sync(0xffffffffu, lr1, 1);
    lr1 += __shfl_xor_sync(0xffffffffu, lr1, 2);
    float inv0 = 1.f / lr0, inv1 = 1.f / lr1;

    int r0 = i0 + wid * 16 + g, r1 = r0 + 8;
#pragma unroll
    for (int ni = 0; ni < 8; ni++) {
        int c = h * DH_ + ni * 8 + q * 2;
        size_t a0 = ((size_t)b * N_ + r0) * D_ + c;
        size_t a1 = ((size_t)b * N_ + r1) * D_ + c;
        *(__half2*)(o + a0) = __floats2half2_rn(oacc[ni][0] * inv0, oacc[ni][1] * inv0);
        *(__half2*)(o + a1) = __floats2half2_rn(oacc[ni][2] * inv1, oacc[ni][3] * inv1);
    }
}

// ---------------- orchestration --------------------------------------------
#define HF_SMEM   (2 * (128 * 144) + 2 * (128 * 144))   /* 73728 -> 2 CTAs/SM */

extern "C" void kernel_launch(void* const* d_in, const int* in_sizes, int n_in,
                              void* d_out, int out_size)
{
    (void)in_sizes; (void)n_in; (void)out_size;
    const float* x     = (const float*)d_in[0];
    const float* ln1_s = (const float*)d_in[1];
    const float* ln1_b = (const float*)d_in[2];
    const float* w_qkv = (const float*)d_in[3];
    const float* w_out = (const float*)d_in[4];
    const float* b_out = (const float*)d_in[5];
    const float* ln2_s = (const float*)d_in[6];
    const float* ln2_b = (const float*)d_in[7];
    const float* w1    = (const float*)d_in[8];
    const float* b1    = (const float*)d_in[9];
    const float* w2    = (const float*)d_in[10];
    const float* b2    = (const float*)d_in[11];
    float* out = (float*)d_out;

    __half *h, *qkv, *vt, *o, *mlp, *wqkv, *wout, *w1t, *w2t;
    cudaGetSymbolAddress((void**)&h,    g_h);
    cudaGetSymbolAddress((void**)&qkv,  g_qkv);
    cudaGetSymbolAddress((void**)&vt,   g_vt);
    cudaGetSymbolAddress((void**)&o,    g_o);
    cudaGetSymbolAddress((void**)&mlp,  g_mlp);
    cudaGetSymbolAddress((void**)&wqkv, g_wqkv);
    cudaGetSymbolAddress((void**)&wout, g_wout);
    cudaGetSymbolAddress((void**)&w1t,  g_w1);
    cudaGetSymbolAddress((void**)&w2t,  g_w2);

    cudaFuncSetAttribute(gemm_hf<0, 1>,
        cudaFuncAttributeMaxDynamicSharedMemorySize, HF_SMEM);
    cudaFuncSetAttribute(gemm_hf<3, 1>,
        cudaFuncAttributeMaxDynamicSharedMemorySize, HF_SMEM);
    cudaFuncSetAttribute(gemm_hf<5, 0>,
        cudaFuncAttributeMaxDynamicSharedMemorySize, HF_SMEM);
    cudaFuncSetAttribute(flash_hf,
        cudaFuncAttributeMaxDynamicSharedMemorySize, FL_SMEM);

    // pre-pass: weights -> [N][K] fp16
    wtrans_kernel<<<dim3(3 * D_ / 32, D_ / 32, DEPTH_), 256>>>(w_qkv, wqkv, D_, 3 * D_);
    wtrans_kernel<<<dim3(D_ / 32, D_ / 32, DEPTH_), 256>>>(w_out, wout, D_, D_);
    wtrans_kernel<<<dim3(MLP_ / 32, D_ / 32, DEPTH_), 256>>>(w1, w1t, D_, MLP_);
    wtrans_kernel<<<dim3(D_ / 32, MLP_ / 32, DEPTH_), 256>>>(w2, w2t, MLP_, D_);

    cudaMemcpyAsync(out, x, (size_t)M_ * D_ * sizeof(float),
                    cudaMemcpyDeviceToDevice);

    for (int l = 0; l < DEPTH_; l++) {
        // --- attention block ---
        ln_kernel<<<M_, 256>>>(out, ln1_s + (size_t)l * D_, ln1_b + (size_t)l * D_, h);
        gemm_hf<0, 1><<<dim3(3 * D_ / 128, M_ / 128), 256, HF_SMEM>>>(
            h, wqkv + (size_t)l * D_ * 3 * D_, nullptr, nullptr,
            qkv, M_, 3 * D_, D_);
        vtrans_kernel<<<dim3(N_ / 64, B_ * H_), 256>>>(qkv, vt);
        flash_hf<<<dim3(N_ / 128, B_ * H_), 256, FL_SMEM>>>(qkv, vt, o);
        gemm_hf<5, 0><<<dim3(D_ / 128, M_ / 128), 256, HF_SMEM>>>(
            o, wout + (size_t)l * D_ * D_, b_out + (size_t)l * D_,
            out, out, M_, D_, D_);
        // --- MLP block ---
        ln_kernel<<<M_, 256>>>(out, ln2_s + (size_t)l * D_, ln2_b + (size_t)l * D_, h);
        gemm_hf<3, 1><<<dim3(MLP_ / 128, M_ / 128), 256, HF_SMEM>>>(
            h, w1t + (size_t)l * D_ * MLP_, b1 + (size_t)l * MLP_,
            nullptr, mlp, M_, MLP_, D_);
        gemm_hf<5, 0><<<dim3(D_ / 128, M_ / 128), 256, HF_SMEM>>>(
            mlp, w2t + (size_t)l * MLP_ * D_, b2 + (size_t)l * D_,
            out, out, M_, D_, MLP_);
    }
}